// round 2
// baseline (speedup 1.0000x reference)
#include <cuda_runtime.h>
#include <cuda_bf16.h>

// DPLoss: mean over B rows of [ sum_{j<len[i]} (pred[i,j]-log(align[i,j]))^2 / len[i] ]
// B=4096, T=2048, fp32. HBM-bound (~67 MB traffic, floor ~8.4us @ 8TB/s).
//
// Single persistent-ish launch: 1024 CTAs (single wave at 8 CTA/SM), each CTA
// owns 4 complete rows -> 16 LDG.128 per thread, deep MLP. One block
// reduction + one device-accumulator atomic per CTA; the last CTA writes the
// final mean and self-resets the accumulator/counter (graph-replay safe).

#define B_ROWS   4096
#define T_COLS   2048
#define T_VEC4   (T_COLS / 4)          // 512 float4 per row
#define NTHREADS 256
#define ROWS_PER_CTA 4
#define NCTAS    (B_ROWS / ROWS_PER_CTA)   // 1024
#define ITERS    (T_VEC4 / NTHREADS)       // 2 per row

__device__ float    g_acc = 0.0f;
__device__ unsigned g_count = 0;

__global__ __launch_bounds__(NTHREADS) void dploss_kernel(
    const float4* __restrict__ pred,
    const float4* __restrict__ align,
    const int* __restrict__ lens,
    float* __restrict__ out)
{
    const int row0 = blockIdx.x * ROWS_PER_CTA;

    float s = 0.0f;

    #pragma unroll
    for (int k = 0; k < ROWS_PER_CTA; ++k) {
        const int row = row0 + k;
        const int len = __ldg(lens + row);
        const float inv_len = 1.0f / (float)len;

        const float4* __restrict__ p = pred  + (size_t)row * T_VEC4;
        const float4* __restrict__ a = align + (size_t)row * T_VEC4;

        float rs = 0.0f;
        #pragma unroll
        for (int it = 0; it < ITERS; ++it) {
            const int i = it * NTHREADS + threadIdx.x;  // vec4 index in row
            const int j = i * 4;                        // element index
            float4 pv = p[i];
            float4 av = a[i];
            float d0 = pv.x - __logf(av.x);
            float d1 = pv.y - __logf(av.y);
            float d2 = pv.z - __logf(av.z);
            float d3 = pv.w - __logf(av.w);
            if (j + 0 < len) rs += d0 * d0;
            if (j + 1 < len) rs += d1 * d1;
            if (j + 2 < len) rs += d2 * d2;
            if (j + 3 < len) rs += d3 * d3;
        }
        s += rs * inv_len;
    }

    // warp reduction
    #pragma unroll
    for (int off = 16; off > 0; off >>= 1)
        s += __shfl_down_sync(0xFFFFFFFFu, s, off);

    // block reduction across 8 warps
    __shared__ float warp_sums[NTHREADS / 32];
    const int wid = threadIdx.x >> 5;
    const int lid = threadIdx.x & 31;
    if (lid == 0) warp_sums[wid] = s;
    __syncthreads();

    if (wid == 0) {
        float v = (lid < NTHREADS / 32) ? warp_sums[lid] : 0.0f;
        #pragma unroll
        for (int off = 4; off > 0; off >>= 1)
            v += __shfl_down_sync(0xFFFFFFFFu, v, off);

        if (lid == 0) {
            atomicAdd(&g_acc, v);
            __threadfence();
            unsigned prev = atomicInc(&g_count, NCTAS - 1);
            if (prev == NCTAS - 1) {
                // last CTA: all adds are visible (fence + atomic ordering)
                float total = atomicExch(&g_acc, 0.0f);   // read + reset
                *out = total * (1.0f / (float)B_ROWS);
            }
        }
    }
}

extern "C" void kernel_launch(void* const* d_in, const int* in_sizes, int n_in,
                              void* d_out, int out_size)
{
    const float4* pred  = (const float4*)d_in[0];
    const float4* align = (const float4*)d_in[1];
    const int*    lens  = (const int*)d_in[2];
    float* out = (float*)d_out;

    dploss_kernel<<<NCTAS, NTHREADS>>>(pred, align, lens, out);
}

// round 4
// speedup vs baseline: 1.0252x; 1.0252x over previous
#include <cuda_runtime.h>
#include <cuda_bf16.h>

// DPLoss: mean over B rows of [ sum_{j<len[i]} (pred[i,j]-log(align[i,j]))^2 / len[i] ]
// B=4096, T=2048, fp32. HBM-bound (~67 MB traffic, floor ~8.4us @ 8TB/s).
//
// R3: exactly-single-wave grid (1184 CTAs = 148 SM x 8 CTA/SM @ 256 thr),
// grid-stride over HALF-ROW work units (8192 units) -> load imbalance is
// <=1 unit (~2%) instead of half a wave (~15%). Tiny loop body keeps regs
// low for full occupancy; lens hits L1 (16 KB). One block reduction +
// device-accumulator atomic per CTA; last CTA writes mean and self-resets.

#define B_ROWS     4096
#define T_COLS     2048
#define T_VEC4     (T_COLS / 4)       // 512 float4 per row
#define NTHREADS   256
#define NCTAS      1184               // 148 SMs * 8 CTAs/SM -> single wave
#define UNITS      (B_ROWS * 2)       // half-row units, 256 float4 each
#define HALF_VEC4  256

__device__ float    g_acc = 0.0f;
__device__ unsigned g_count = 0;

__global__ __launch_bounds__(NTHREADS, 8) void dploss_kernel(
    const float4* __restrict__ pred,
    const float4* __restrict__ align,
    const int* __restrict__ lens,
    float* __restrict__ out)
{
    float s = 0.0f;

    for (int u = blockIdx.x; u < UNITS; u += NCTAS) {
        const int row = u >> 1;
        const int i   = ((u & 1) << 8) | threadIdx.x;   // vec4 index in row
        const int j   = i << 2;                          // element index in row

        const int len = __ldg(lens + row);
        const size_t base = (size_t)row * T_VEC4 + i;
        float4 pv = pred[base];
        float4 av = align[base];

        const float inv_len = 1.0f / (float)len;

        float d0 = pv.x - __logf(av.x);
        float d1 = pv.y - __logf(av.y);
        float d2 = pv.z - __logf(av.z);
        float d3 = pv.w - __logf(av.w);

        float rs = 0.0f;
        if (j + 0 < len) rs += d0 * d0;
        if (j + 1 < len) rs += d1 * d1;
        if (j + 2 < len) rs += d2 * d2;
        if (j + 3 < len) rs += d3 * d3;

        s += rs * inv_len;
    }

    // warp reduction
    #pragma unroll
    for (int off = 16; off > 0; off >>= 1)
        s += __shfl_down_sync(0xFFFFFFFFu, s, off);

    // block reduction across 8 warps
    __shared__ float warp_sums[NTHREADS / 32];
    const int wid = threadIdx.x >> 5;
    const int lid = threadIdx.x & 31;
    if (lid == 0) warp_sums[wid] = s;
    __syncthreads();

    if (wid == 0) {
        float v = (lid < NTHREADS / 32) ? warp_sums[lid] : 0.0f;
        #pragma unroll
        for (int off = 4; off > 0; off >>= 1)
            v += __shfl_down_sync(0xFFFFFFFFu, v, off);

        if (lid == 0) {
            atomicAdd(&g_acc, v);
            __threadfence();
            unsigned prev = atomicInc(&g_count, NCTAS - 1);
            if (prev == NCTAS - 1) {
                float total = atomicExch(&g_acc, 0.0f);   // read + reset for replay
                *out = total * (1.0f / (float)B_ROWS);
            }
        }
    }
}

extern "C" void kernel_launch(void* const* d_in, const int* in_sizes, int n_in,
                              void* d_out, int out_size)
{
    const float4* pred  = (const float4*)d_in[0];
    const float4* align = (const float4*)d_in[1];
    const int*    lens  = (const int*)d_in[2];
    float* out = (float*)d_out;

    dploss_kernel<<<NCTAS, NTHREADS>>>(pred, align, lens, out);
}